// round 1
// baseline (speedup 1.0000x reference)
#include <cuda_runtime.h>
#include <cstdint>

#define BB 4
#define SS 2048
#define DDIM 1024
#define HH 16
#define DKK 64
#define MTOT (BB*SS)   // 8192

// ---------------- scratch (static __device__, allocation-free) ----------------
__device__ float g_Q[(size_t)BB*SS*DDIM];
__device__ float g_K[(size_t)BB*SS*DDIM];
__device__ float g_V[(size_t)BB*SS*DDIM];
__device__ float g_A[(size_t)BB*SS*DDIM];

// ---------------- helpers ----------------
__device__ __forceinline__ uint32_t f2tf32(float f) {
    uint32_t u;
    asm("cvt.rna.tf32.f32 %0, %1;" : "=r"(u) : "f"(f));
    return u;
}

__device__ __forceinline__ float ex2(float x) {
    float y;
    asm("ex2.approx.ftz.f32 %0, %1;" : "=f"(y) : "f"(x));
    return y;
}

// D(16x8,f32) += A(16x8,tf32,row) * B(8x8,tf32,col)
__device__ __forceinline__ void mma_tf32(float c[4],
                                         uint32_t a0, uint32_t a1, uint32_t a2, uint32_t a3,
                                         uint32_t b0, uint32_t b1) {
    asm volatile(
        "mma.sync.aligned.m16n8k8.row.col.f32.tf32.tf32.f32 "
        "{%0,%1,%2,%3}, {%4,%5,%6,%7}, {%8,%9}, {%0,%1,%2,%3};"
        : "+f"(c[0]), "+f"(c[1]), "+f"(c[2]), "+f"(c[3])
        : "r"(a0), "r"(a1), "r"(a2), "r"(a3), "r"(b0), "r"(b1));
}

// ---------------- GEMM: C[m][n] = sum_k A[m][k] * W[n][k]  (M x 1024, K=N=1024) ----------------
#define GBM 128
#define GBN 128
#define GBK 32
#define GST (GBK + 4)   // 36 -> conflict-free fragment loads

__global__ __launch_bounds__(256, 1)
void gemm_nt(const float* __restrict__ A, const float* __restrict__ W,
             float* __restrict__ C) {
    __shared__ uint32_t As[GBM][GST];
    __shared__ uint32_t Bs[GBN][GST];

    const int m0 = blockIdx.y * GBM;
    const int n0 = blockIdx.x * GBN;
    const int tid = threadIdx.x;
    const int w = tid >> 5, lane = tid & 31;
    const int g = lane >> 2, tig = lane & 3;
    const int wm = (w >> 2) * 64;   // 2 warp-rows
    const int wn = (w & 3) * 32;    // 4 warp-cols

    float acc[4][4][4];
#pragma unroll
    for (int i = 0; i < 4; i++)
#pragma unroll
        for (int j = 0; j < 4; j++)
#pragma unroll
            for (int e = 0; e < 4; e++) acc[i][j][e] = 0.f;

    const int lr = tid >> 3;          // 0..31
    const int lc = (tid & 7) << 2;    // 0,4,..,28

    for (int k0 = 0; k0 < DDIM; k0 += GBK) {
        __syncthreads();
#pragma unroll
        for (int it = 0; it < 4; it++) {
            int row = lr + it * 32;
            float4 va = *reinterpret_cast<const float4*>(&A[(size_t)(m0 + row) * DDIM + k0 + lc]);
            As[row][lc + 0] = f2tf32(va.x); As[row][lc + 1] = f2tf32(va.y);
            As[row][lc + 2] = f2tf32(va.z); As[row][lc + 3] = f2tf32(va.w);
            float4 vb = *reinterpret_cast<const float4*>(&W[(size_t)(n0 + row) * DDIM + k0 + lc]);
            Bs[row][lc + 0] = f2tf32(vb.x); Bs[row][lc + 1] = f2tf32(vb.y);
            Bs[row][lc + 2] = f2tf32(vb.z); Bs[row][lc + 3] = f2tf32(vb.w);
        }
        __syncthreads();

#pragma unroll
        for (int ks = 0; ks < 4; ks++) {
            const int kk = ks * 8;
            uint32_t b[4][2];
#pragma unroll
            for (int nt = 0; nt < 4; nt++) {
                int n = wn + nt * 8 + g;
                b[nt][0] = Bs[n][kk + tig];
                b[nt][1] = Bs[n][kk + tig + 4];
            }
#pragma unroll
            for (int mt = 0; mt < 4; mt++) {
                int m = wm + mt * 16 + g;
                uint32_t a0 = As[m][kk + tig];
                uint32_t a1 = As[m + 8][kk + tig];
                uint32_t a2 = As[m][kk + tig + 4];
                uint32_t a3 = As[m + 8][kk + tig + 4];
#pragma unroll
                for (int nt = 0; nt < 4; nt++)
                    mma_tf32(acc[mt][nt], a0, a1, a2, a3, b[nt][0], b[nt][1]);
            }
        }
    }

#pragma unroll
    for (int mt = 0; mt < 4; mt++) {
        int r0 = m0 + wm + mt * 16 + g;
#pragma unroll
        for (int nt = 0; nt < 4; nt++) {
            int col = n0 + wn + nt * 8 + 2 * tig;
            *reinterpret_cast<float2*>(&C[(size_t)r0 * DDIM + col]) =
                make_float2(acc[mt][nt][0], acc[mt][nt][1]);
            *reinterpret_cast<float2*>(&C[(size_t)(r0 + 8) * DDIM + col]) =
                make_float2(acc[mt][nt][2], acc[mt][nt][3]);
        }
    }
}

// ---------------- flash attention (causal + padding mask), tf32 mma ----------------
#define AP 68                       // padded row stride (words)
#define ASMEM (4 * 64 * AP * 4 + 64 * 4)

__global__ __launch_bounds__(128, 1)
void attn_kernel(const float* __restrict__ Q, const float* __restrict__ K,
                 const float* __restrict__ V, const int* __restrict__ mask,
                 float* __restrict__ O) {
    extern __shared__ uint32_t smem_u[];
    uint32_t* Qs = smem_u;
    uint32_t* Ks = Qs + 64 * AP;
    uint32_t* Vs = Ks + 64 * AP;
    uint32_t* Ps = Vs + 64 * AP;
    int* msk = (int*)(Ps + 64 * AP);

    const int qi = blockIdx.x;       // 0..31 : query tile
    const int bh = blockIdx.y;       // 0..63
    const int b = bh / HH, h = bh % HH;

    const int tid = threadIdx.x;
    const int w = tid >> 5, lane = tid & 31;
    const int g = lane >> 2, tig = lane & 3;
    const int w16 = w * 16;

    const float* Qb = Q + ((size_t)b * SS + (size_t)qi * 64) * DDIM + h * DKK;
    const float* Kb = K + (size_t)b * SS * DDIM + h * DKK;
    const float* Vb = V + (size_t)b * SS * DDIM + h * DKK;
    float* Ob = O + ((size_t)b * SS + (size_t)qi * 64) * DDIM + h * DKK;

    // scale = 1/sqrt(DK) * log2(e), folded into Q so softmax uses exp2
    const float qscale = 0.125f * 1.4426950408889634f;

    // load Q tile (64 rows x 64 dims)
#pragma unroll
    for (int t = 0; t < 8; t++) {
        int i = tid + t * 128;
        int r = i >> 4;
        int c4 = (i & 15) << 2;
        float4 v = *reinterpret_cast<const float4*>(Qb + (size_t)r * DDIM + c4);
        uint32_t* p = &Qs[r * AP + c4];
        p[0] = f2tf32(v.x * qscale); p[1] = f2tf32(v.y * qscale);
        p[2] = f2tf32(v.z * qscale); p[3] = f2tf32(v.w * qscale);
    }

    float mrow0 = -1e30f, mrow1 = -1e30f;
    float lrow0 = 0.f, lrow1 = 0.f;
    float o[8][4];
#pragma unroll
    for (int nt = 0; nt < 8; nt++)
#pragma unroll
        for (int e = 0; e < 4; e++) o[nt][e] = 0.f;

    const int q0 = qi * 64 + w16 + g;
    const int q1 = q0 + 8;

    for (int kt = 0; kt <= qi; kt++) {
        __syncthreads();
        // load K/V tiles (64 keys x 64 dims) + mask slice
        const float* Kt = Kb + (size_t)kt * 64 * DDIM;
        const float* Vt = Vb + (size_t)kt * 64 * DDIM;
#pragma unroll
        for (int t = 0; t < 8; t++) {
            int i = tid + t * 128;
            int r = i >> 4;
            int c4 = (i & 15) << 2;
            float4 vk = *reinterpret_cast<const float4*>(Kt + (size_t)r * DDIM + c4);
            uint32_t* pk = &Ks[r * AP + c4];
            pk[0] = f2tf32(vk.x); pk[1] = f2tf32(vk.y);
            pk[2] = f2tf32(vk.z); pk[3] = f2tf32(vk.w);
            float4 vv = *reinterpret_cast<const float4*>(Vt + (size_t)r * DDIM + c4);
            uint32_t* pv = &Vs[r * AP + c4];
            pv[0] = f2tf32(vv.x); pv[1] = f2tf32(vv.y);
            pv[2] = f2tf32(vv.z); pv[3] = f2tf32(vv.w);
        }
        if (tid < 64) msk[tid] = mask[(size_t)b * SS + kt * 64 + tid];
        __syncthreads();

        // scores S = Q' @ K^T  (16x64 per warp)
        float s[8][4];
#pragma unroll
        for (int nt = 0; nt < 8; nt++) { s[nt][0] = s[nt][1] = s[nt][2] = s[nt][3] = 0.f; }
#pragma unroll
        for (int ks = 0; ks < 8; ks++) {
            int kk = ks * 8;
            uint32_t a0 = Qs[(w16 + g) * AP + kk + tig];
            uint32_t a1 = Qs[(w16 + g + 8) * AP + kk + tig];
            uint32_t a2 = Qs[(w16 + g) * AP + kk + tig + 4];
            uint32_t a3 = Qs[(w16 + g + 8) * AP + kk + tig + 4];
#pragma unroll
            for (int nt = 0; nt < 8; nt++) {
                uint32_t b0 = Ks[(nt * 8 + g) * AP + kk + tig];
                uint32_t b1 = Ks[(nt * 8 + g) * AP + kk + tig + 4];
                mma_tf32(s[nt], a0, a1, a2, a3, b0, b1);
            }
        }

        // masking (causal on diagonal tile + padding mask)
        const bool diag = (kt == qi);
#pragma unroll
        for (int nt = 0; nt < 8; nt++) {
            int cl = nt * 8 + 2 * tig;
            int cg = kt * 64 + cl;
            bool mv0 = (msk[cl] != 0);
            bool mv1 = (msk[cl + 1] != 0);
            if (!mv0 || (diag && cg > q0))     s[nt][0] = -1e30f;
            if (!mv1 || (diag && cg + 1 > q0)) s[nt][1] = -1e30f;
            if (!mv0 || (diag && cg > q1))     s[nt][2] = -1e30f;
            if (!mv1 || (diag && cg + 1 > q1)) s[nt][3] = -1e30f;
        }

        // online softmax (base 2)
        float rm0 = -1e30f, rm1 = -1e30f;
#pragma unroll
        for (int nt = 0; nt < 8; nt++) {
            rm0 = fmaxf(rm0, fmaxf(s[nt][0], s[nt][1]));
            rm1 = fmaxf(rm1, fmaxf(s[nt][2], s[nt][3]));
        }
        rm0 = fmaxf(rm0, __shfl_xor_sync(0xffffffffu, rm0, 1));
        rm0 = fmaxf(rm0, __shfl_xor_sync(0xffffffffu, rm0, 2));
        rm1 = fmaxf(rm1, __shfl_xor_sync(0xffffffffu, rm1, 1));
        rm1 = fmaxf(rm1, __shfl_xor_sync(0xffffffffu, rm1, 2));

        float mn0 = fmaxf(mrow0, rm0);
        float mn1 = fmaxf(mrow1, rm1);
        float al0 = ex2(mrow0 - mn0);
        float al1 = ex2(mrow1 - mn1);
        mrow0 = mn0; mrow1 = mn1;

        float rs0 = 0.f, rs1 = 0.f;
#pragma unroll
        for (int nt = 0; nt < 8; nt++) {
            int cl = nt * 8 + 2 * tig;
            float p0 = ex2(s[nt][0] - mn0);
            float p1 = ex2(s[nt][1] - mn0);
            float p2 = ex2(s[nt][2] - mn1);
            float p3 = ex2(s[nt][3] - mn1);
            rs0 += p0 + p1;
            rs1 += p2 + p3;
            Ps[(w16 + g) * AP + cl]     = f2tf32(p0);
            Ps[(w16 + g) * AP + cl + 1] = f2tf32(p1);
            Ps[(w16 + g + 8) * AP + cl]     = f2tf32(p2);
            Ps[(w16 + g + 8) * AP + cl + 1] = f2tf32(p3);
        }
        rs0 += __shfl_xor_sync(0xffffffffu, rs0, 1);
        rs0 += __shfl_xor_sync(0xffffffffu, rs0, 2);
        rs1 += __shfl_xor_sync(0xffffffffu, rs1, 1);
        rs1 += __shfl_xor_sync(0xffffffffu, rs1, 2);
        lrow0 = lrow0 * al0 + rs0;
        lrow1 = lrow1 * al1 + rs1;

#pragma unroll
        for (int nt = 0; nt < 8; nt++) {
            o[nt][0] *= al0; o[nt][1] *= al0;
            o[nt][2] *= al1; o[nt][3] *= al1;
        }
        __syncwarp();

        // O += P @ V   (k = keys, n = dims)
#pragma unroll
        for (int ks = 0; ks < 8; ks++) {
            int kk = ks * 8;
            uint32_t a0 = Ps[(w16 + g) * AP + kk + tig];
            uint32_t a1 = Ps[(w16 + g + 8) * AP + kk + tig];
            uint32_t a2 = Ps[(w16 + g) * AP + kk + tig + 4];
            uint32_t a3 = Ps[(w16 + g + 8) * AP + kk + tig + 4];
#pragma unroll
            for (int nt = 0; nt < 8; nt++) {
                uint32_t b0 = Vs[(kk + tig) * AP + nt * 8 + g];
                uint32_t b1 = Vs[(kk + tig + 4) * AP + nt * 8 + g];
                mma_tf32(o[nt], a0, a1, a2, a3, b0, b1);
            }
        }
    }

    // normalize + store
    float i0 = 1.f / lrow0;
    float i1 = 1.f / lrow1;
    int r0 = w16 + g;
#pragma unroll
    for (int nt = 0; nt < 8; nt++) {
        int cl = nt * 8 + 2 * tig;
        *reinterpret_cast<float2*>(&Ob[(size_t)r0 * DDIM + cl]) =
            make_float2(o[nt][0] * i0, o[nt][1] * i0);
        *reinterpret_cast<float2*>(&Ob[(size_t)(r0 + 8) * DDIM + cl]) =
            make_float2(o[nt][2] * i1, o[nt][3] * i1);
    }
}

// ---------------- launch ----------------
extern "C" void kernel_launch(void* const* d_in, const int* in_sizes, int n_in,
                              void* d_out, int out_size) {
    const float* xq = (const float*)d_in[0];
    const float* xk = (const float*)d_in[1];
    const float* xv = (const float*)d_in[2];
    const int* mask = (const int*)d_in[3];
    const float* Wq = (const float*)d_in[4];
    const float* Wk = (const float*)d_in[5];
    const float* Wv = (const float*)d_in[6];
    const float* Wo = (const float*)d_in[7];
    float* out = (float*)d_out;

    float *Qp, *Kp, *Vp, *Ap;
    cudaGetSymbolAddress((void**)&Qp, g_Q);
    cudaGetSymbolAddress((void**)&Kp, g_K);
    cudaGetSymbolAddress((void**)&Vp, g_V);
    cudaGetSymbolAddress((void**)&Ap, g_A);

    cudaFuncSetAttribute(attn_kernel, cudaFuncAttributeMaxDynamicSharedMemorySize, ASMEM);

    dim3 gg(DDIM / GBN, MTOT / GBM);   // (8, 64)
    gemm_nt<<<gg, 256>>>(xq, Wq, Qp);
    gemm_nt<<<gg, 256>>>(xk, Wk, Kp);
    gemm_nt<<<gg, 256>>>(xv, Wv, Vp);

    attn_kernel<<<dim3(SS / 64, BB * HH), 128, ASMEM>>>(Qp, Kp, Vp, mask, Ap);

    gemm_nt<<<gg, 256>>>(Ap, Wo, out);
}

// round 2
// speedup vs baseline: 1.6219x; 1.6219x over previous
#include <cuda_runtime.h>
#include <cstdint>

#define BB 4
#define SS 2048
#define DDIM 1024
#define HH 16
#define DKK 64
#define MTOT (BB*SS)   // 8192

// ---------------- scratch (static __device__, allocation-free) ----------------
__device__ float g_Q[(size_t)BB*SS*DDIM];
__device__ float g_K[(size_t)BB*SS*DDIM];
__device__ float g_V[(size_t)BB*SS*DDIM];
__device__ float g_A[(size_t)BB*SS*DDIM];

// ---------------- helpers ----------------
__device__ __forceinline__ uint32_t f2tf32(float f) {
    uint32_t u;
    asm("cvt.rna.tf32.f32 %0, %1;" : "=r"(u) : "f"(f));
    return u;
}

__device__ __forceinline__ float ex2(float x) {
    float y;
    asm("ex2.approx.ftz.f32 %0, %1;" : "=f"(y) : "f"(x));
    return y;
}

__device__ __forceinline__ void cp16(uint32_t saddr, const void* g) {
    asm volatile("cp.async.cg.shared.global [%0], [%1], 16;" :: "r"(saddr), "l"(g));
}
__device__ __forceinline__ void cp_commit() {
    asm volatile("cp.async.commit_group;");
}
template <int N>
__device__ __forceinline__ void cp_wait() {
    asm volatile("cp.async.wait_group %0;" :: "n"(N));
}

// D(16x8,f32) += A(16x8,tf32,row) * B(8x8,tf32,col)
__device__ __forceinline__ void mma_tf32(float c[4],
                                         uint32_t a0, uint32_t a1, uint32_t a2, uint32_t a3,
                                         uint32_t b0, uint32_t b1) {
    asm volatile(
        "mma.sync.aligned.m16n8k8.row.col.f32.tf32.tf32.f32 "
        "{%0,%1,%2,%3}, {%4,%5,%6,%7}, {%8,%9}, {%0,%1,%2,%3};"
        : "+f"(c[0]), "+f"(c[1]), "+f"(c[2]), "+f"(c[3])
        : "r"(a0), "r"(a1), "r"(a2), "r"(a3), "r"(b0), "r"(b1));
}

// ---------------- GEMM: C[m][n] = sum_k A[m][k] * W[n][k], 2-stage cp.async ----------------
#define GBM 128
#define GBN 128
#define GBK 32
#define GST (GBK + 4)                       // 36 floats stride, 144B (16B aligned)
#define GSTAGE (GBM * GST)                  // floats per stage per matrix
#define GSMEM (4 * GSTAGE * 4)              // bytes: 2 matrices x 2 stages

__global__ __launch_bounds__(256, 1)
void gemm_nt(const float* __restrict__ A0, const float* __restrict__ A1, const float* __restrict__ A2,
             const float* __restrict__ W0, const float* __restrict__ W1, const float* __restrict__ W2,
             float* __restrict__ C0, float* __restrict__ C1, float* __restrict__ C2) {
    extern __shared__ float gsm[];
    float* Asm = gsm;                 // 2 stages of [GBM][GST]
    float* Bsm = gsm + 2 * GSTAGE;    // 2 stages of [GBN][GST]

    const int z = blockIdx.z;
    const float* A = (z == 0) ? A0 : (z == 1) ? A1 : A2;
    const float* W = (z == 0) ? W0 : (z == 1) ? W1 : W2;
    float*       C = (z == 0) ? C0 : (z == 1) ? C1 : C2;

    const int m0 = blockIdx.y * GBM;
    const int n0 = blockIdx.x * GBN;
    const int tid = threadIdx.x;
    const int w = tid >> 5, lane = tid & 31;
    const int g = lane >> 2, tig = lane & 3;
    const int wm = (w >> 2) * 64;
    const int wn = (w & 3) * 32;

    const int lr = tid >> 3;          // 0..31
    const int lc = (tid & 7) << 2;    // 0,4,..,28

    const uint32_t sA = (uint32_t)__cvta_generic_to_shared(Asm);
    const uint32_t sB = (uint32_t)__cvta_generic_to_shared(Bsm);

    float acc[4][4][4];
#pragma unroll
    for (int i = 0; i < 4; i++)
#pragma unroll
        for (int j = 0; j < 4; j++)
#pragma unroll
            for (int e = 0; e < 4; e++) acc[i][j][e] = 0.f;

    auto issue = [&](int st, int k0) {
#pragma unroll
        for (int it = 0; it < 4; it++) {
            int row = lr + it * 32;
            cp16(sA + (uint32_t)((st * GBM + row) * GST + lc) * 4,
                 &A[(size_t)(m0 + row) * DDIM + k0 + lc]);
            cp16(sB + (uint32_t)((st * GBN + row) * GST + lc) * 4,
                 &W[(size_t)(n0 + row) * DDIM + k0 + lc]);
        }
    };

    issue(0, 0);
    cp_commit();

    const int NKT = DDIM / GBK;       // 32
    for (int kt = 0; kt < NKT; kt++) {
        const int cur = kt & 1;
        if (kt + 1 < NKT) {
            issue((kt + 1) & 1, (kt + 1) * GBK);
            cp_commit();
            cp_wait<1>();
        } else {
            cp_wait<0>();
        }
        __syncthreads();

        const float* Ac = Asm + cur * GSTAGE;
        const float* Bc = Bsm + cur * GSTAGE;

#pragma unroll
        for (int ks = 0; ks < 4; ks++) {
            const int kk = ks * 8;
            uint32_t b[4][2];
#pragma unroll
            for (int nt = 0; nt < 4; nt++) {
                int n = wn + nt * 8 + g;
                b[nt][0] = f2tf32(Bc[n * GST + kk + tig]);
                b[nt][1] = f2tf32(Bc[n * GST + kk + tig + 4]);
            }
#pragma unroll
            for (int mt = 0; mt < 4; mt++) {
                int m = wm + mt * 16 + g;
                uint32_t a0 = f2tf32(Ac[m * GST + kk + tig]);
                uint32_t a1 = f2tf32(Ac[(m + 8) * GST + kk + tig]);
                uint32_t a2 = f2tf32(Ac[m * GST + kk + tig + 4]);
                uint32_t a3 = f2tf32(Ac[(m + 8) * GST + kk + tig + 4]);
#pragma unroll
                for (int nt = 0; nt < 4; nt++)
                    mma_tf32(acc[mt][nt], a0, a1, a2, a3, b[nt][0], b[nt][1]);
            }
        }
        __syncthreads();
    }

#pragma unroll
    for (int mt = 0; mt < 4; mt++) {
        int r0 = m0 + wm + mt * 16 + g;
#pragma unroll
        for (int nt = 0; nt < 4; nt++) {
            int col = n0 + wn + nt * 8 + 2 * tig;
            *reinterpret_cast<float2*>(&C[(size_t)r0 * DDIM + col]) =
                make_float2(acc[mt][nt][0], acc[mt][nt][1]);
            *reinterpret_cast<float2*>(&C[(size_t)(r0 + 8) * DDIM + col]) =
                make_float2(acc[mt][nt][2], acc[mt][nt][3]);
        }
    }
}

// ---------------- flash attention: 128-row Q tile, 32 rows/warp, Q frags in regs ----------------
#define AQT 128
#define AKT 64
#define AP 68
#define ASMEM ((64 + 64 + 128) * AP * 4 + 64 * 4)

__global__ __launch_bounds__(128, 1)
void attn_kernel(const float* __restrict__ Q, const float* __restrict__ K,
                 const float* __restrict__ V, const int* __restrict__ mask,
                 float* __restrict__ O) {
    extern __shared__ uint32_t smem_u[];
    uint32_t* Ks = smem_u;
    uint32_t* Vs = Ks + 64 * AP;
    uint32_t* Ps = Vs + 64 * AP;              // 128 rows (also Q staging)
    int* msk = (int*)(Ps + 128 * AP);

    const int qi = blockIdx.x;                // 0..15
    const int bh = blockIdx.y;                // 0..63
    const int b = bh / HH, h = bh % HH;

    const int tid = threadIdx.x;
    const int w = tid >> 5, lane = tid & 31;
    const int g = lane >> 2, tig = lane & 3;
    const int wrow = w * 32;

    const float* Qb = Q + ((size_t)b * SS + (size_t)qi * AQT) * DDIM + h * DKK;
    const float* Kb = K + (size_t)b * SS * DDIM + h * DKK;
    const float* Vb = V + (size_t)b * SS * DDIM + h * DKK;
    float* Ob = O + ((size_t)b * SS + (size_t)qi * AQT) * DDIM + h * DKK;

    const float qscale = 0.125f * 1.4426950408889634f;

    // stage Q (128x64) through Ps, then pull fragments into registers
#pragma unroll
    for (int t = 0; t < 16; t++) {
        int i = tid + t * 128;
        int r = i >> 4;
        int c4 = (i & 15) << 2;
        float4 v = *reinterpret_cast<const float4*>(Qb + (size_t)r * DDIM + c4);
        uint32_t* p = &Ps[r * AP + c4];
        p[0] = f2tf32(v.x * qscale); p[1] = f2tf32(v.y * qscale);
        p[2] = f2tf32(v.z * qscale); p[3] = f2tf32(v.w * qscale);
    }
    __syncthreads();

    uint32_t qf[2][8][4];
#pragma unroll
    for (int mt = 0; mt < 2; mt++) {
        int r = wrow + mt * 16;
#pragma unroll
        for (int ks = 0; ks < 8; ks++) {
            int kk = ks * 8;
            qf[mt][ks][0] = Ps[(r + g) * AP + kk + tig];
            qf[mt][ks][1] = Ps[(r + g + 8) * AP + kk + tig];
            qf[mt][ks][2] = Ps[(r + g) * AP + kk + tig + 4];
            qf[mt][ks][3] = Ps[(r + g + 8) * AP + kk + tig + 4];
        }
    }
    __syncthreads();

    float mrow[2][2], lrow[2][2];
    float o[2][8][4];
#pragma unroll
    for (int mt = 0; mt < 2; mt++) {
        mrow[mt][0] = mrow[mt][1] = -1e30f;
        lrow[mt][0] = lrow[mt][1] = 0.f;
#pragma unroll
        for (int nt = 0; nt < 8; nt++)
#pragma unroll
            for (int e = 0; e < 4; e++) o[mt][nt][e] = 0.f;
    }

    const int ktmax = 2 * qi + 1;
    const int rowmax = qi * AQT + wrow + 31;   // highest query row of this warp

    for (int kt = 0; kt <= ktmax; kt++) {
        __syncthreads();
        const float* Kt = Kb + (size_t)kt * 64 * DDIM;
        const float* Vt = Vb + (size_t)kt * 64 * DDIM;
#pragma unroll
        for (int t = 0; t < 8; t++) {
            int i = tid + t * 128;
            int r = i >> 4;
            int c4 = (i & 15) << 2;
            float4 vk = *reinterpret_cast<const float4*>(Kt + (size_t)r * DDIM + c4);
            uint32_t* pk = &Ks[r * AP + c4];
            pk[0] = f2tf32(vk.x); pk[1] = f2tf32(vk.y);
            pk[2] = f2tf32(vk.z); pk[3] = f2tf32(vk.w);
            float4 vv = *reinterpret_cast<const float4*>(Vt + (size_t)r * DDIM + c4);
            uint32_t* pv = &Vs[r * AP + c4];
            pv[0] = f2tf32(vv.x); pv[1] = f2tf32(vv.y);
            pv[2] = f2tf32(vv.z); pv[3] = f2tf32(vv.w);
        }
        if (tid < 64) msk[tid] = mask[(size_t)b * SS + kt * 64 + tid];
        __syncthreads();

        if (kt * 64 > rowmax) continue;   // warp-uniform skip of fully-masked tiles

        // S = Q @ K^T : 32x64 per warp (2 m-tiles)
        float s[2][8][4];
#pragma unroll
        for (int mt = 0; mt < 2; mt++)
#pragma unroll
            for (int nt = 0; nt < 8; nt++)
                s[mt][nt][0] = s[mt][nt][1] = s[mt][nt][2] = s[mt][nt][3] = 0.f;

#pragma unroll
        for (int ks = 0; ks < 8; ks++) {
            int kk = ks * 8;
            uint32_t bf[8][2];
#pragma unroll
            for (int nt = 0; nt < 8; nt++) {
                bf[nt][0] = Ks[(nt * 8 + g) * AP + kk + tig];
                bf[nt][1] = Ks[(nt * 8 + g) * AP + kk + tig + 4];
            }
#pragma unroll
            for (int mt = 0; mt < 2; mt++)
#pragma unroll
                for (int nt = 0; nt < 8; nt++)
                    mma_tf32(s[mt][nt], qf[mt][ks][0], qf[mt][ks][1],
                             qf[mt][ks][2], qf[mt][ks][3], bf[nt][0], bf[nt][1]);
        }

        // masking + online softmax per m-tile
#pragma unroll
        for (int mt = 0; mt < 2; mt++) {
            const int q0 = qi * AQT + wrow + mt * 16 + g;
            const int q1 = q0 + 8;
            const bool needc = (kt * 64 + 63 > qi * AQT + wrow + mt * 16);
#pragma unroll
            for (int nt = 0; nt < 8; nt++) {
                int cl = nt * 8 + 2 * tig;
                int cg = kt * 64 + cl;
                bool mv0 = (msk[cl] != 0);
                bool mv1 = (msk[cl + 1] != 0);
                if (!mv0 || (needc && cg > q0))     s[mt][nt][0] = -1e30f;
                if (!mv1 || (needc && cg + 1 > q0)) s[mt][nt][1] = -1e30f;
                if (!mv0 || (needc && cg > q1))     s[mt][nt][2] = -1e30f;
                if (!mv1 || (needc && cg + 1 > q1)) s[mt][nt][3] = -1e30f;
            }

            float rm0 = -1e30f, rm1 = -1e30f;
#pragma unroll
            for (int nt = 0; nt < 8; nt++) {
                rm0 = fmaxf(rm0, fmaxf(s[mt][nt][0], s[mt][nt][1]));
                rm1 = fmaxf(rm1, fmaxf(s[mt][nt][2], s[mt][nt][3]));
            }
            rm0 = fmaxf(rm0, __shfl_xor_sync(0xffffffffu, rm0, 1));
            rm0 = fmaxf(rm0, __shfl_xor_sync(0xffffffffu, rm0, 2));
            rm1 = fmaxf(rm1, __shfl_xor_sync(0xffffffffu, rm1, 1));
            rm1 = fmaxf(rm1, __shfl_xor_sync(0xffffffffu, rm1, 2));

            float mn0 = fmaxf(mrow[mt][0], rm0);
            float mn1 = fmaxf(mrow[mt][1], rm1);
            float al0 = ex2(mrow[mt][0] - mn0);
            float al1 = ex2(mrow[mt][1] - mn1);
            mrow[mt][0] = mn0; mrow[mt][1] = mn1;

            float rs0 = 0.f, rs1 = 0.f;
            const int pr = wrow + mt * 16;
#pragma unroll
            for (int nt = 0; nt < 8; nt++) {
                int cl = nt * 8 + 2 * tig;
                float p0 = ex2(s[mt][nt][0] - mn0);
                float p1 = ex2(s[mt][nt][1] - mn0);
                float p2 = ex2(s[mt][nt][2] - mn1);
                float p3 = ex2(s[mt][nt][3] - mn1);
                rs0 += p0 + p1;
                rs1 += p2 + p3;
                Ps[(pr + g) * AP + cl]         = f2tf32(p0);
                Ps[(pr + g) * AP + cl + 1]     = f2tf32(p1);
                Ps[(pr + g + 8) * AP + cl]     = f2tf32(p2);
                Ps[(pr + g + 8) * AP + cl + 1] = f2tf32(p3);
            }
            rs0 += __shfl_xor_sync(0xffffffffu, rs0, 1);
            rs0 += __shfl_xor_sync(0xffffffffu, rs0, 2);
            rs1 += __shfl_xor_sync(0xffffffffu, rs1, 1);
            rs1 += __shfl_xor_sync(0xffffffffu, rs1, 2);
            lrow[mt][0] = lrow[mt][0] * al0 + rs0;
            lrow[mt][1] = lrow[mt][1] * al1 + rs1;

#pragma unroll
            for (int nt = 0; nt < 8; nt++) {
                o[mt][nt][0] *= al0; o[mt][nt][1] *= al0;
                o[mt][nt][2] *= al1; o[mt][nt][3] *= al1;
            }
        }
        __syncwarp();

        // O += P @ V
#pragma unroll
        for (int ks = 0; ks < 8; ks++) {
            int kk = ks * 8;
            uint32_t vb[8][2];
#pragma unroll
            for (int nt = 0; nt < 8; nt++) {
                vb[nt][0] = Vs[(kk + tig) * AP + nt * 8 + g];
                vb[nt][1] = Vs[(kk + tig + 4) * AP + nt * 8 + g];
            }
#pragma unroll
            for (int mt = 0; mt < 2; mt++) {
                const int pr = wrow + mt * 16;
                uint32_t a0 = Ps[(pr + g) * AP + kk + tig];
                uint32_t a1 = Ps[(pr + g + 8) * AP + kk + tig];
                uint32_t a2 = Ps[(pr + g) * AP + kk + tig + 4];
                uint32_t a3 = Ps[(pr + g + 8) * AP + kk + tig + 4];
#pragma unroll
                for (int nt = 0; nt < 8; nt++)
                    mma_tf32(o[mt][nt], a0, a1, a2, a3, vb[nt][0], vb[nt][1]);
            }
        }
    }

    // normalize + store
#pragma unroll
    for (int mt = 0; mt < 2; mt++) {
        float i0 = 1.f / lrow[mt][0];
        float i1 = 1.f / lrow[mt][1];
        int r0 = wrow + mt * 16 + g;
#pragma unroll
        for (int nt = 0; nt < 8; nt++) {
            int cl = nt * 8 + 2 * tig;
            *reinterpret_cast<float2*>(&Ob[(size_t)r0 * DDIM + cl]) =
                make_float2(o[mt][nt][0] * i0, o[mt][nt][1] * i0);
            *reinterpret_cast<float2*>(&Ob[(size_t)(r0 + 8) * DDIM + cl]) =
                make_float2(o[mt][nt][2] * i1, o[mt][nt][3] * i1);
        }
    }
}

// ---------------- launch ----------------
extern "C" void kernel_launch(void* const* d_in, const int* in_sizes, int n_in,
                              void* d_out, int out_size) {
    const float* xq = (const float*)d_in[0];
    const float* xk = (const float*)d_in[1];
    const float* xv = (const float*)d_in[2];
    const int* mask = (const int*)d_in[3];
    const float* Wq = (const float*)d_in[4];
    const float* Wk = (const float*)d_in[5];
    const float* Wv = (const float*)d_in[6];
    const float* Wo = (const float*)d_in[7];
    float* out = (float*)d_out;

    float *Qp, *Kp, *Vp, *Ap;
    cudaGetSymbolAddress((void**)&Qp, g_Q);
    cudaGetSymbolAddress((void**)&Kp, g_K);
    cudaGetSymbolAddress((void**)&Vp, g_V);
    cudaGetSymbolAddress((void**)&Ap, g_A);

    cudaFuncSetAttribute(gemm_nt, cudaFuncAttributeMaxDynamicSharedMemorySize, GSMEM);
    cudaFuncSetAttribute(attn_kernel, cudaFuncAttributeMaxDynamicSharedMemorySize, ASMEM);

    // fused QKV projections (gridDim.z selects the GEMM)
    gemm_nt<<<dim3(DDIM / GBN, MTOT / GBM, 3), 256, GSMEM>>>(
        xq, xk, xv, Wq, Wk, Wv, Qp, Kp, Vp);

    attn_kernel<<<dim3(SS / AQT, BB * HH), 128, ASMEM>>>(Qp, Kp, Vp, mask, Ap);

    gemm_nt<<<dim3(DDIM / GBN, MTOT / GBM, 1), 256, GSMEM>>>(
        Ap, Ap, Ap, Wo, Wo, Wo, out, out, out);
}